// round 10
// baseline (speedup 1.0000x reference)
#include <cuda_runtime.h>
#include <math.h>

#define NT 1024
#define CD 768
#define NH 16
#define DH 48
#define HD 1536
#define CPD 128

typedef unsigned long long ull;

// ---------------- f32x2 packed-math helpers (sm_100+) -----------------------
__device__ __forceinline__ ull pk2(float lo, float hi) {
    ull r; asm("mov.b64 %0, {%1, %2};" : "=l"(r) : "f"(lo), "f"(hi)); return r;
}
__device__ __forceinline__ void fma2(ull &d, ull a, ull b) {
    asm("fma.rn.f32x2 %0, %1, %2, %0;" : "+l"(d) : "l"(a), "l"(b));
}
__device__ __forceinline__ ull add2(ull a, ull b) {
    ull r; asm("add.rn.f32x2 %0, %1, %2;" : "=l"(r) : "l"(a), "l"(b)); return r;
}
__device__ __forceinline__ ull mul2(ull a, ull b) {
    ull r; asm("mul.rn.f32x2 %0, %1, %2;" : "=l"(r) : "l"(a), "l"(b)); return r;
}
__device__ __forceinline__ float2 up2(ull v) {
    float2 r; asm("mov.b64 {%0, %1}, %2;" : "=f"(r.x), "=f"(r.y) : "l"(v)); return r;
}
__device__ __forceinline__ float sigm(float x) { return 1.f/(1.f+__expf(-x)); }

// ---------------- scratch (device globals; no allocations allowed) ----------
__device__ __align__(16) float g_lna[NT*CD];
__device__ __align__(16) float g_sn1[NT*CD];
__device__ __align__(16) float g_sn2[NT*CD];
__device__ __align__(16) float g_an[NT*CD];
__device__ __align__(16) float g_o[NT*CD];
__device__ __align__(16) float g_attout[2*NT*CD];    // split-K partials
__device__ __align__(16) float g_bout[NT*CD];
__device__ __align__(16) float g_h1[NT*HD];
__device__ __align__(16) float g_t3[2*NT*CD];        // split-K partials
__device__ __align__(16) float g_tgk[NT*2*CD];       // tg|tk packed, stride 1536
__device__ __align__(16) float g_qkvg[NT*4*CD];      // q|k|v|gate, stride 3072
__device__ __align__(16) float g_ts2[NT*2*CD];       // s@wso | s@ws2, stride 1536
__device__ __align__(16) float g_h12[NT*2*HD];       // h1|h2, stride 3072
__device__ __align__(16) float g_bqkv[4*CD];
__device__ __align__(16) float g_wgp[CPD*NH];
__device__ __align__(16) ull   g_wpk[8*CPD];         // packed h-pairs
__device__ __align__(16) float g_cc[2*NH];
__device__ __align__(16) float g_bias[(size_t)NH*NT*NT];   // 64 MB [h][q][k]

// ---------------- LayerNorm of a and s; sn1 = LN(s)*sg1, sn2 = LN(s)*sg2 ----
__global__ void ln_kernel(const float* __restrict__ a, const float* __restrict__ s,
                          const float* __restrict__ sg1, const float* __restrict__ sg2)
{
    int r = blockIdx.x, t = threadIdx.x;
    const float* ar = a + (size_t)r*CD;
    const float* sr = s + (size_t)r*CD;
    float va[3], vs[3];
    float s0=0.f,s1=0.f,s2=0.f,s3=0.f;
#pragma unroll
    for (int i=0;i<3;i++){
        va[i]=ar[t+256*i]; vs[i]=sr[t+256*i];
        s0+=va[i]; s1+=va[i]*va[i]; s2+=vs[i]; s3+=vs[i]*vs[i];
    }
    __shared__ float red[4][8];
    int lane=t&31, w=t>>5;
#pragma unroll
    for (int o=16;o;o>>=1){
        s0+=__shfl_xor_sync(0xffffffffu,s0,o);
        s1+=__shfl_xor_sync(0xffffffffu,s1,o);
        s2+=__shfl_xor_sync(0xffffffffu,s2,o);
        s3+=__shfl_xor_sync(0xffffffffu,s3,o);
    }
    if (lane==0){ red[0][w]=s0; red[1][w]=s1; red[2][w]=s2; red[3][w]=s3; }
    __syncthreads();
    float S0=0.f,S1=0.f,S2=0.f,S3=0.f;
#pragma unroll
    for (int i=0;i<8;i++){ S0+=red[0][i]; S1+=red[1][i]; S2+=red[2][i]; S3+=red[3][i]; }
    float mua=S0*(1.f/768.f), rsa=rsqrtf(S1*(1.f/768.f)-mua*mua+1e-5f);
    float mus=S2*(1.f/768.f), rss=rsqrtf(S3*(1.f/768.f)-mus*mus+1e-5f);
#pragma unroll
    for (int i=0;i<3;i++){
        int c=t+256*i; size_t idx=(size_t)r*CD+c;
        g_lna[idx]=(va[i]-mua)*rsa;
        float sv=(vs[i]-mus)*rss;
        g_sn1[idx]=sv*sg1[c];
        g_sn2[idx]=sv*sg2[c];
    }
}

__global__ void bfill_kernel(const float* __restrict__ bq)
{
    int i = blockIdx.x*256 + threadIdx.x;
    g_bqkv[i] = (i < CD) ? bq[i] : 0.f;
}

// ---------------- SGEMM: 64x64 tile, 64 threads, 8x8/thread, f32x2 ----------
// As stored DUPLICATED (row r at floats 2r,2r+1) so ulonglong2 LDS.128 yields
// packed (a,a) pairs directly; B pairs contiguous. Zero packing movs.
__global__ void __launch_bounds__(64) sgemm64_kernel(
    const float* __restrict__ A, int lda,
    const float* __restrict__ B0, const float* __restrict__ B1,
    const float* __restrict__ B2, const float* __restrict__ B3,
    int bN, const float* __restrict__ biasv,
    float* __restrict__ C, int Nn, int K, int cz)
{
    __shared__ __align__(16) float As[2][8][128];
    __shared__ __align__(16) float Bs[2][8][64];
    int t = threadIdx.x;
    int z = blockIdx.z;
    int tx = t & 7, ty = t >> 3;
    int row0 = blockIdx.y << 6;
    int cb = blockIdx.x;
    int perSrc = bN >> 6;
    int si = cb / perSrc;
    const float* Bsel = (si==0) ? B0 : (si==1) ? B1 : (si==2) ? B2 : B3;
    int colSrc = (cb - si*perSrc) << 6;

    const float* Ag = A + (size_t)(row0 + t)*lda + (size_t)z*K;
    const float* Bg = Bsel + (size_t)z*K*bN + (size_t)(t>>3)*bN + colSrc + ((t&7)<<2);
    C += (size_t)z*cz;

    ull acc[8][4];
#pragma unroll
    for (int i=0;i<8;i++)
#pragma unroll
        for (int j=0;j<4;j++) acc[i][j]=0ull;

    int nt = K >> 3;
    float4 a0 = *(const float4*)(Ag);
    float4 a1 = *(const float4*)(Ag + 4);
    float4 b0 = *(const float4*)(Bg);
    float4 b1 = *(const float4*)(Bg + 32);
    {
        int t2 = t<<1;
        *(float2*)&As[0][0][t2] = make_float2(a0.x,a0.x);
        *(float2*)&As[0][1][t2] = make_float2(a0.y,a0.y);
        *(float2*)&As[0][2][t2] = make_float2(a0.z,a0.z);
        *(float2*)&As[0][3][t2] = make_float2(a0.w,a0.w);
        *(float2*)&As[0][4][t2] = make_float2(a1.x,a1.x);
        *(float2*)&As[0][5][t2] = make_float2(a1.y,a1.y);
        *(float2*)&As[0][6][t2] = make_float2(a1.z,a1.z);
        *(float2*)&As[0][7][t2] = make_float2(a1.w,a1.w);
        *(float4*)&Bs[0][t>>3][(t&7)<<2] = b0;
        *(float4*)&Bs[0][t>>3][((t&7)<<2)+32] = b1;
    }
    __syncthreads();

    for (int kt = 0; kt < nt; kt++) {
        int cur = kt & 1;
        bool more = (kt+1) < nt;
        if (more) {
            a0 = *(const float4*)(Ag + (kt+1)*8);
            a1 = *(const float4*)(Ag + (kt+1)*8 + 4);
            b0 = *(const float4*)(Bg + (size_t)(kt+1)*8*bN);
            b1 = *(const float4*)(Bg + (size_t)(kt+1)*8*bN + 32);
        }
#pragma unroll
        for (int kk = 0; kk < 8; kk++) {
            const float* Ar = &As[cur][kk][ty<<4];
            ulonglong2 A0v = *(const ulonglong2*)(Ar);
            ulonglong2 A1v = *(const ulonglong2*)(Ar+4);
            ulonglong2 A2v = *(const ulonglong2*)(Ar+8);
            ulonglong2 A3v = *(const ulonglong2*)(Ar+12);
            const float* Br = &Bs[cur][kk][tx<<3];
            ulonglong2 B0v = *(const ulonglong2*)(Br);
            ulonglong2 B1v = *(const ulonglong2*)(Br+4);
            ull aa[8] = {A0v.x,A0v.y,A1v.x,A1v.y,A2v.x,A2v.y,A3v.x,A3v.y};
#pragma unroll
            for (int i=0;i<8;i++){
                fma2(acc[i][0], aa[i], B0v.x);
                fma2(acc[i][1], aa[i], B0v.y);
                fma2(acc[i][2], aa[i], B1v.x);
                fma2(acc[i][3], aa[i], B1v.y);
            }
        }
        if (more) {
            int nx = cur ^ 1;
            int t2 = t<<1;
            *(float2*)&As[nx][0][t2] = make_float2(a0.x,a0.x);
            *(float2*)&As[nx][1][t2] = make_float2(a0.y,a0.y);
            *(float2*)&As[nx][2][t2] = make_float2(a0.z,a0.z);
            *(float2*)&As[nx][3][t2] = make_float2(a0.w,a0.w);
            *(float2*)&As[nx][4][t2] = make_float2(a1.x,a1.x);
            *(float2*)&As[nx][5][t2] = make_float2(a1.y,a1.y);
            *(float2*)&As[nx][6][t2] = make_float2(a1.z,a1.z);
            *(float2*)&As[nx][7][t2] = make_float2(a1.w,a1.w);
            *(float4*)&Bs[nx][t>>3][(t&7)<<2] = b0;
            *(float4*)&Bs[nx][t>>3][((t&7)<<2)+32] = b1;
            __syncthreads();
        }
    }

    int col = (cb<<6) + (tx<<3);
    float4 bb0 = make_float4(0.f,0.f,0.f,0.f), bb1 = bb0;
    if (biasv) { bb0 = *(const float4*)(biasv + col); bb1 = *(const float4*)(biasv + col + 4); }
#pragma unroll
    for (int i=0;i<8;i++){
        int r = row0 + (ty<<3) + i;
        float2 p0=up2(acc[i][0]), p1=up2(acc[i][1]), p2=up2(acc[i][2]), p3=up2(acc[i][3]);
        float4 o0 = make_float4(p0.x+bb0.x, p0.y+bb0.y, p1.x+bb0.z, p1.y+bb0.w);
        float4 o1 = make_float4(p2.x+bb1.x, p2.y+bb1.y, p3.x+bb1.z, p3.y+bb1.w);
        *(float4*)(C + (size_t)r*Nn + col) = o0;
        *(float4*)(C + (size_t)r*Nn + col + 4) = o1;
    }
}

// ---------------- adaLN combine: an = sigmoid(tg+bg)*lna + tk ---------------
__global__ void adaln_combine_kernel(const float* __restrict__ tgk,
                                     const float* __restrict__ bgv,
                                     float* __restrict__ outp)
{
    int i = blockIdx.x*256 + threadIdx.x;
    int r = i / CD, c = i - r*CD;
    float tg = tgk[(size_t)r*1536 + c];
    float tk = tgk[(size_t)r*1536 + 768 + c];
    outp[i] = sigm(tg + bgv[c])*g_lna[i] + tk;
}

// ---------------- pair-bias precompute: wgp, packed h-pairs, c1/c2 ----------
__global__ void pair_prep_kernel(const float* __restrict__ gp,
                                 const float* __restrict__ bp,
                                 const float* __restrict__ wp)
{
    int j = threadIdx.x;  // 128
    float wg[NH];
#pragma unroll
    for (int h=0; h<NH; h++){ wg[h] = gp[j]*wp[j*NH+h]; g_wgp[j*NH+h] = wg[h]; }
#pragma unroll
    for (int m=0; m<8; m++) g_wpk[m*CPD + j] = pk2(wg[2*m], wg[2*m+1]);
    __syncthreads();
    if (j < NH) {
        float c1=0.f, c2=0.f;
        for (int jj=0; jj<CPD; jj++){ c1 += bp[jj]*wp[jj*NH+j]; c2 += g_wgp[jj*NH+j]; }
        g_cc[j]=c1; g_cc[NH+j]=c2;
    }
}

// ---------------- pair bias v3b: thread owns 4 pairs, weights broadcast -----
#define PB_SMEM (512*36*4 + 128*8*8)
__global__ void __launch_bounds__(128) pair_bias_kernel(
    const float* __restrict__ pair, const float* __restrict__ beta)
{
    extern __shared__ __align__(16) float smem[];
    float* xs = smem;                         // [512][36]
    ull* wks = (ull*)(smem + 512*36);         // [128 k][8 m]
    __shared__ float csm[2*NH];

    int t = threadIdx.x;
    int q = blockIdx.x >> 1;
    int k0 = (blockIdx.x & 1) << 9;

    for (int i = t; i < 1024; i += 128) {
        int k = i >> 3, m = i & 7;
        wks[(k<<3) + m] = g_wpk[m*CPD + k];
    }
    if (t < 2*NH) csm[t] = g_cc[t];

    ull acc[4][8];
#pragma unroll
    for (int i=0;i<4;i++)
#pragma unroll
        for (int m=0;m<8;m++) acc[i][m]=0ull;
    float sm[4] = {0.f,0.f,0.f,0.f};
    float sq[4] = {0.f,0.f,0.f,0.f};

    const float* base = pair + (((size_t)q<<10) + k0)*CPD;

    for (int c = 0; c < 4; c++) {
        __syncthreads();
#pragma unroll
        for (int it=0; it<32; it++) {
            int g = (it<<7) + t;
            int row = g >> 3, j = g & 7;
            *(float4*)(xs + row*36 + (j<<2)) =
                *(const float4*)(base + (size_t)row*CPD + (c<<5) + (j<<2));
        }
        __syncthreads();
#pragma unroll
        for (int kk=0; kk<32; kk++) {
            const ull* wr = wks + ((c<<5)+kk)*8;
            ull w0=wr[0], w1=wr[1], w2=wr[2], w3=wr[3];
            ull w4=wr[4], w5=wr[5], w6=wr[6], w7=wr[7];
#pragma unroll
            for (int i=0;i<4;i++){
                float xv = xs[(t + (i<<7))*36 + kk];
                sm[i] += xv;
                sq[i] = fmaf(xv, xv, sq[i]);
                ull xx = pk2(xv, xv);
                fma2(acc[i][0], xx, w0); fma2(acc[i][1], xx, w1);
                fma2(acc[i][2], xx, w2); fma2(acc[i][3], xx, w3);
                fma2(acc[i][4], xx, w4); fma2(acc[i][5], xx, w5);
                fma2(acc[i][6], xx, w6); fma2(acc[i][7], xx, w7);
            }
        }
    }

#pragma unroll
    for (int i=0;i<4;i++){
        int p = t + (i<<7);
        int kk = k0 + p;
        float mu = sm[i]*(1.f/128.f);
        float rs = rsqrtf(sq[i]*(1.f/128.f) - mu*mu + 1e-5f);
        float murs = mu*rs;
        float bv = beta[((size_t)q<<10) + kk];
#pragma unroll
        for (int m=0;m<8;m++){
            float2 v = up2(acc[i][m]);
            int h0 = m<<1;
            float z0 = rs*v.x - murs*csm[NH+h0]   + csm[h0]   + bv;
            float z1 = rs*v.y - murs*csm[NH+h0+1] + csm[h0+1] + bv;
            g_bias[((size_t)h0<<20)     + ((size_t)q<<10) + kk] = z0;
            g_bias[((size_t)(h0+1)<<20) + ((size_t)q<<10) + kk] = z1;
        }
    }
}

// ---------------- flash attention v2: 32 q-rows x 4 k-quarters --------------
// grid (32,16); 128 threads: qrow = t&31, quarter = t>>5 (one warp/quarter ->
// all smem K/V reads are warp-broadcast). Dot uses 4 accumulators (short dep
// chain). 3-way merge by quarter 0; fused output gate.
__global__ void __launch_bounds__(128) attn_kernel(
    const float* __restrict__ qp, const float* __restrict__ kp,
    const float* __restrict__ vp, const float* __restrict__ gatep)
{
    __shared__ __align__(16) float poolK[6144];   // [4 quarters][32 rows][48]
    __shared__ __align__(16) float poolV[6144];
    int t = threadIdx.x;
    int qrow = t & 31, quarter = t >> 5;
    int h = blockIdx.y;
    int qr = (blockIdx.x<<5) + qrow;
    const float scale = 0.14433756729740643f;
    ull q2[24];
#pragma unroll
    for (int d4=0; d4<12; d4++){
        float4 qq = *(const float4*)(qp + (size_t)qr*3072 + h*48 + (d4<<2));
        q2[d4*2]   = pk2(qq.x*scale, qq.y*scale);
        q2[d4*2+1] = pk2(qq.z*scale, qq.w*scale);
    }
    float m = -1e30f, l = 0.f;
    ull acc2[24];
#pragma unroll
    for (int i=0;i<24;i++) acc2[i]=0ull;
    const float* brow = g_bias + ((size_t)h<<20) + ((size_t)qr<<10) + (quarter<<8);

    for (int tile=0; tile<8; tile++) {
        int kt = tile<<5;
        __syncthreads();
#pragma unroll
        for (int it=0; it<12; it++) {
            int s = t + (it<<7);              // 0..1535
            int d4 = s % 12;
            int row = s / 12;                 // 0..127
            int krow = ((row>>5)<<8) + kt + (row&31);
            ((float4*)poolK)[s] = *(const float4*)(kp + (size_t)krow*3072 + h*48 + (d4<<2));
            ((float4*)poolV)[s] = *(const float4*)(vp + (size_t)krow*3072 + h*48 + (d4<<2));
        }
        __syncthreads();
        float bb[32];
#pragma unroll
        for (int i=0;i<8;i++){
            float4 b4 = *(const float4*)(brow + kt + (i<<2));
            bb[i*4]=b4.x; bb[i*4+1]=b4.y; bb[i*4+2]=b4.z; bb[i*4+3]=b4.w;
        }
        const float* Kt = poolK + quarter*1536;
        const float* Vt = poolV + quarter*1536;
        for (int j=0; j<32; j++) {
            const ull* kr2 = (const ull*)(Kt + j*48);
            ull da=0ull, db=0ull, dc=0ull, dd4=0ull;
#pragma unroll
            for (int i=0;i<6;i++){
                fma2(da,  q2[i],    kr2[i]);
                fma2(db,  q2[i+6],  kr2[i+6]);
                fma2(dc,  q2[i+12], kr2[i+12]);
                fma2(dd4, q2[i+18], kr2[i+18]);
            }
            da = add2(da, db); dc = add2(dc, dd4); da = add2(da, dc);
            float2 ds = up2(da);
            float sc = ds.x + ds.y + bb[j];
            if (sc > m) {
                float corr = __expf(m - sc);
                l *= corr;
                ull cp = pk2(corr, corr);
#pragma unroll
                for (int i=0;i<24;i++) acc2[i] = mul2(acc2[i], cp);
                m = sc;
            }
            float pw = __expf(sc - m);
            l += pw;
            ull pp = pk2(pw, pw);
            const ull* vr2 = (const ull*)(Vt + j*48);
#pragma unroll
            for (int i=0;i<24;i++) fma2(acc2[i], pp, vr2[i]);
        }
    }

    // ---- merge 4 quarters (reuse poolK as buffers) ----
    __syncthreads();
    float* bufM = poolK;             // [3][32]
    float* bufL = poolK + 96;        // [3][32]
    float* bufA = poolK + 192;       // [3][32][48]
    if (quarter > 0) {
        int b = (quarter-1)*32 + qrow;
        bufM[b] = m; bufL[b] = l;
#pragma unroll
        for (int i=0;i<24;i++){
            float2 v = up2(acc2[i]);
            bufA[b*48 + 2*i]   = v.x;
            bufA[b*48 + 2*i+1] = v.y;
        }
    }
    __syncthreads();
    if (quarter == 0) {
        float M = m, L = l, Aacc[48];
#pragma unroll
        for (int i=0;i<24;i++){
            float2 v = up2(acc2[i]);
            Aacc[2*i] = v.x; Aacc[2*i+1] = v.y;
        }
        for (int qq=0; qq<3; qq++){
            int b = qq*32 + qrow;
            float m2 = bufM[b], l2 = bufL[b];
            float mn = fmaxf(M, m2);
            float c1 = __expf(M - mn), c2 = __expf(m2 - mn);
            L = L*c1 + l2*c2;
#pragma unroll
            for (int d=0; d<48; d++)
                Aacc[d] = Aacc[d]*c1 + bufA[b*48+d]*c2;
            M = mn;
        }
        float inv = 1.f/L;
#pragma unroll
        for (int d=0; d<48; d++){
            float g0 = sigm(gatep[(size_t)qr*3072 + h*48 + d]);
            g_o[(size_t)qr*CD + h*48 + d] = Aacc[d]*inv*g0;
        }
    }
}

// ---------------- small elementwise kernels ---------------------------------
__global__ void bout_kernel(const float* __restrict__ bso) {
    int i = blockIdx.x*256 + threadIdx.x;
    int r = i / CD, c = i - r*CD;
    float att = g_attout[i] + g_attout[NT*CD + i];
    g_bout[i] = sigm(g_ts2[(size_t)r*1536 + c] + bso[c])*att;
}
__global__ void swiglu_kernel() {
    int i = blockIdx.x*256 + threadIdx.x;
    int r = i / HD, c = i - r*HD;
    float x = g_h12[(size_t)r*3072 + c];
    float y = g_h12[(size_t)r*3072 + 1536 + c];
    g_h1[i] = x*sigm(x)*y;
}
__global__ void final_kernel(const float* __restrict__ bs2, float* __restrict__ outp) {
    int i = blockIdx.x*256 + threadIdx.x;
    int r = i / CD, c = i - r*CD;
    float t3 = g_t3[i] + g_t3[NT*CD + i];
    outp[i] = g_bout[i] + sigm(g_ts2[(size_t)r*1536 + 768 + c] + bs2[c])*t3;
}

// ---------------- launch ----------------------------------------------------
extern "C" void kernel_launch(void* const* d_in, const int* in_sizes, int n_in,
                              void* d_out, int out_size)
{
    (void)in_sizes; (void)n_in; (void)out_size;
    const float* a     = (const float*)d_in[0];
    const float* s     = (const float*)d_in[1];
    const float* pair  = (const float*)d_in[2];
    const float* beta  = (const float*)d_in[3];
    const float* sg1   = (const float*)d_in[4];
    const float* wg1   = (const float*)d_in[5];
    const float* bg1   = (const float*)d_in[6];
    const float* wsk1  = (const float*)d_in[7];
    const float* wq    = (const float*)d_in[8];
    const float* bq    = (const float*)d_in[9];
    const float* wk    = (const float*)d_in[10];
    const float* wv    = (const float*)d_in[11];
    const float* gp    = (const float*)d_in[12];
    const float* bp    = (const float*)d_in[13];
    const float* wp    = (const float*)d_in[14];
    const float* wgate = (const float*)d_in[15];
    const float* wo    = (const float*)d_in[16];
    const float* wso   = (const float*)d_in[17];
    const float* bso   = (const float*)d_in[18];
    const float* sg2   = (const float*)d_in[19];
    const float* wg2   = (const float*)d_in[20];
    const float* bg2   = (const float*)d_in[21];
    const float* wsk2  = (const float*)d_in[22];
    const float* w1    = (const float*)d_in[23];
    const float* w2    = (const float*)d_in[24];
    const float* w3    = (const float*)d_in[25];
    const float* ws2   = (const float*)d_in[26];
    const float* bs2   = (const float*)d_in[27];

    float *p_sn1,*p_sn2,*p_an,*p_o,*p_attout,*p_h1,*p_t3,*p_tgk,*p_qkvg,*p_ts2,*p_h12,*p_bqkv;
    cudaGetSymbolAddress((void**)&p_sn1,   g_sn1);
    cudaGetSymbolAddress((void**)&p_sn2,   g_sn2);
    cudaGetSymbolAddress((void**)&p_an,    g_an);
    cudaGetSymbolAddress((void**)&p_o,     g_o);
    cudaGetSymbolAddress((void**)&p_attout,g_attout);
    cudaGetSymbolAddress((void**)&p_h1,    g_h1);
    cudaGetSymbolAddress((void**)&p_t3,    g_t3);
    cudaGetSymbolAddress((void**)&p_tgk,   g_tgk);
    cudaGetSymbolAddress((void**)&p_qkvg,  g_qkvg);
    cudaGetSymbolAddress((void**)&p_ts2,   g_ts2);
    cudaGetSymbolAddress((void**)&p_h12,   g_h12);
    cudaGetSymbolAddress((void**)&p_bqkv,  g_bqkv);

    static int smem_set = 0;
    if (!smem_set) {
        cudaFuncSetAttribute(pair_bias_kernel,
                             cudaFuncAttributeMaxDynamicSharedMemorySize, PB_SMEM);
        smem_set = 1;
    }

    // ---- prep ----
    ln_kernel<<<NT, 256>>>(a, s, sg1, sg2);
    pair_prep_kernel<<<1, 128>>>(gp, bp, wp);
    bfill_kernel<<<12, 256>>>(bq);

    // ---- pair bias (independent long pole) ----
    pair_bias_kernel<<<2048, 128, PB_SMEM>>>(pair, beta);

    // ---- AttentionPairBias ----
    sgemm64_kernel<<<dim3(24,16,1), 64>>>(p_sn1, CD, wg1, wsk1, wg1, wg1, CD,
                                          nullptr, p_tgk, 1536, CD, 0);
    adaln_combine_kernel<<<NT*CD/256, 256>>>(p_tgk, bg1, p_an);
    sgemm64_kernel<<<dim3(48,16,1), 64>>>(p_an, CD, wq, wk, wv, wgate, CD,
                                          p_bqkv, p_qkvg, 3072, CD, 0);
    attn_kernel<<<dim3(32, 16), 128>>>(p_qkvg, p_qkvg + 768, p_qkvg + 1536, p_qkvg + 2304);
    sgemm64_kernel<<<dim3(12,16,2), 64>>>(p_o, CD, wo, wo, wo, wo, CD,
                                          nullptr, p_attout, CD, 384, NT*CD);
    sgemm64_kernel<<<dim3(24,16,1), 64>>>(s, CD, wso, ws2, wso, wso, CD,
                                          nullptr, p_ts2, 1536, CD, 0);
    bout_kernel<<<NT*CD/256, 256>>>(bso);

    // ---- ConditionedTransitionBlock ----
    sgemm64_kernel<<<dim3(24,16,1), 64>>>(p_sn2, CD, wg2, wsk2, wg2, wg2, CD,
                                          nullptr, p_tgk, 1536, CD, 0);
    adaln_combine_kernel<<<NT*CD/256, 256>>>(p_tgk, bg2, p_an);
    sgemm64_kernel<<<dim3(48,16,1), 64>>>(p_an, CD, w1, w2, w1, w1, HD,
                                          nullptr, p_h12, 3072, CD, 0);
    swiglu_kernel<<<NT*HD/256, 256>>>();
    sgemm64_kernel<<<dim3(12,16,2), 64>>>(p_h1, HD, w3, w3, w3, w3, CD,
                                          nullptr, p_t3, CD, CD, NT*CD);
    final_kernel<<<NT*CD/256, 256>>>(bs2, (float*)d_out);
}

// round 11
// speedup vs baseline: 1.2388x; 1.2388x over previous
#include <cuda_runtime.h>
#include <math.h>

#define NT 1024
#define CD 768
#define NH 16
#define DH 48
#define HD 1536
#define CPD 128

typedef unsigned long long ull;

// ---------------- f32x2 packed-math helpers (sm_100+) -----------------------
__device__ __forceinline__ ull pk2(float lo, float hi) {
    ull r; asm("mov.b64 %0, {%1, %2};" : "=l"(r) : "f"(lo), "f"(hi)); return r;
}
__device__ __forceinline__ void fma2(ull &d, ull a, ull b) {
    asm("fma.rn.f32x2 %0, %1, %2, %0;" : "+l"(d) : "l"(a), "l"(b));
}
__device__ __forceinline__ ull add2(ull a, ull b) {
    ull r; asm("add.rn.f32x2 %0, %1, %2;" : "=l"(r) : "l"(a), "l"(b)); return r;
}
__device__ __forceinline__ ull mul2(ull a, ull b) {
    ull r; asm("mul.rn.f32x2 %0, %1, %2;" : "=l"(r) : "l"(a), "l"(b)); return r;
}
__device__ __forceinline__ float2 up2(ull v) {
    float2 r; asm("mov.b64 {%0, %1}, %2;" : "=f"(r.x), "=f"(r.y) : "l"(v)); return r;
}
__device__ __forceinline__ float sigm(float x) { return 1.f/(1.f+__expf(-x)); }

// ---------------- scratch (device globals; no allocations allowed) ----------
__device__ __align__(16) float g_lna[NT*CD];
__device__ __align__(16) float g_sn1[NT*CD];
__device__ __align__(16) float g_sn2[NT*CD];
__device__ __align__(16) float g_an[NT*CD];
__device__ __align__(16) float g_an2[NT*CD];
__device__ __align__(16) float g_o[NT*CD];
__device__ __align__(16) float g_attout[2*NT*CD];    // split-K partials
__device__ __align__(16) float g_bout[NT*CD];
__device__ __align__(16) float g_h1[NT*HD];
__device__ __align__(16) float g_t3[2*NT*CD];        // split-K partials
__device__ __align__(16) float g_tgk[NT*2*CD];       // attn adaLN tg|tk, stride 1536
__device__ __align__(16) float g_tgk2[NT*2*CD];      // transition adaLN tg|tk
__device__ __align__(16) float g_qkvg[NT*4*CD];      // q|k|v|gate, stride 3072
__device__ __align__(16) float g_ts2[NT*2*CD];       // s@wso | s@ws2, stride 1536
__device__ __align__(16) float g_h12[NT*2*HD];       // h1|h2, stride 3072
__device__ __align__(16) float g_bqkv[4*CD];
__device__ __align__(16) float g_wgp[CPD*NH];
__device__ __align__(16) ull   g_wpk[8*CPD];         // packed h-pairs
__device__ __align__(16) float g_cc[2*NH];
__device__ __align__(16) float g_bias[(size_t)NH*NT*NT];   // 64 MB [h][q][k]

// ---------------- LayerNorm of a and s; sn1 = LN(s)*sg1, sn2 = LN(s)*sg2 ----
__global__ void ln_kernel(const float* __restrict__ a, const float* __restrict__ s,
                          const float* __restrict__ sg1, const float* __restrict__ sg2)
{
    int r = blockIdx.x, t = threadIdx.x;
    const float* ar = a + (size_t)r*CD;
    const float* sr = s + (size_t)r*CD;
    float va[3], vs[3];
    float s0=0.f,s1=0.f,s2=0.f,s3=0.f;
#pragma unroll
    for (int i=0;i<3;i++){
        va[i]=ar[t+256*i]; vs[i]=sr[t+256*i];
        s0+=va[i]; s1+=va[i]*va[i]; s2+=vs[i]; s3+=vs[i]*vs[i];
    }
    __shared__ float red[4][8];
    int lane=t&31, w=t>>5;
#pragma unroll
    for (int o=16;o;o>>=1){
        s0+=__shfl_xor_sync(0xffffffffu,s0,o);
        s1+=__shfl_xor_sync(0xffffffffu,s1,o);
        s2+=__shfl_xor_sync(0xffffffffu,s2,o);
        s3+=__shfl_xor_sync(0xffffffffu,s3,o);
    }
    if (lane==0){ red[0][w]=s0; red[1][w]=s1; red[2][w]=s2; red[3][w]=s3; }
    __syncthreads();
    float S0=0.f,S1=0.f,S2=0.f,S3=0.f;
#pragma unroll
    for (int i=0;i<8;i++){ S0+=red[0][i]; S1+=red[1][i]; S2+=red[2][i]; S3+=red[3][i]; }
    float mua=S0*(1.f/768.f), rsa=rsqrtf(S1*(1.f/768.f)-mua*mua+1e-5f);
    float mus=S2*(1.f/768.f), rss=rsqrtf(S3*(1.f/768.f)-mus*mus+1e-5f);
#pragma unroll
    for (int i=0;i<3;i++){
        int c=t+256*i; size_t idx=(size_t)r*CD+c;
        g_lna[idx]=(va[i]-mua)*rsa;
        float sv=(vs[i]-mus)*rss;
        g_sn1[idx]=sv*sg1[c];
        g_sn2[idx]=sv*sg2[c];
    }
}

__global__ void bfill_kernel(const float* __restrict__ bq)
{
    int i = blockIdx.x*256 + threadIdx.x;
    g_bqkv[i] = (i < CD) ? bq[i] : 0.f;
}

// ---------------- SGEMM: 64x64 tile, 64 threads, 8x8/thread, f32x2 (R9) -----
__global__ void __launch_bounds__(64) sgemm64_kernel(
    const float* __restrict__ A, int lda,
    const float* __restrict__ B0, const float* __restrict__ B1,
    const float* __restrict__ B2, const float* __restrict__ B3,
    int bN, const float* __restrict__ biasv,
    float* __restrict__ C, int Nn, int K, int cz)
{
    __shared__ __align__(16) float As[2][8][64];
    __shared__ __align__(16) float Bs[2][8][64];
    int t = threadIdx.x;
    int z = blockIdx.z;
    int tx = t & 7, ty = t >> 3;
    int row0 = blockIdx.y << 6;
    int cb = blockIdx.x;
    int perSrc = bN >> 6;
    int si = cb / perSrc;
    const float* Bsel = (si==0) ? B0 : (si==1) ? B1 : (si==2) ? B2 : B3;
    int colSrc = (cb - si*perSrc) << 6;

    const float* Ag = A + (size_t)(row0 + t)*lda + (size_t)z*K;
    const float* Bg = Bsel + (size_t)z*K*bN + (size_t)(t>>3)*bN + colSrc + ((t&7)<<2);
    C += (size_t)z*cz;

    ull acc[8][4];
#pragma unroll
    for (int i=0;i<8;i++)
#pragma unroll
        for (int j=0;j<4;j++) acc[i][j]=0ull;

    int nt = K >> 3;
    float4 a0 = *(const float4*)(Ag);
    float4 a1 = *(const float4*)(Ag + 4);
    float4 b0 = *(const float4*)(Bg);
    float4 b1 = *(const float4*)(Bg + 32);
    {
        As[0][0][t]=a0.x; As[0][1][t]=a0.y; As[0][2][t]=a0.z; As[0][3][t]=a0.w;
        As[0][4][t]=a1.x; As[0][5][t]=a1.y; As[0][6][t]=a1.z; As[0][7][t]=a1.w;
        *(float4*)&Bs[0][t>>3][(t&7)<<2] = b0;
        *(float4*)&Bs[0][t>>3][((t&7)<<2)+32] = b1;
    }
    __syncthreads();

    for (int kt = 0; kt < nt; kt++) {
        int cur = kt & 1;
        bool more = (kt+1) < nt;
        if (more) {
            a0 = *(const float4*)(Ag + (kt+1)*8);
            a1 = *(const float4*)(Ag + (kt+1)*8 + 4);
            b0 = *(const float4*)(Bg + (size_t)(kt+1)*8*bN);
            b1 = *(const float4*)(Bg + (size_t)(kt+1)*8*bN + 32);
        }
#pragma unroll
        for (int kk = 0; kk < 8; kk++) {
            float4 av0 = *(const float4*)&As[cur][kk][ty<<3];
            float4 av1 = *(const float4*)&As[cur][kk][(ty<<3)+4];
            float4 bv0 = *(const float4*)&Bs[cur][kk][tx<<3];
            float4 bv1 = *(const float4*)&Bs[cur][kk][(tx<<3)+4];
            ull bp0 = pk2(bv0.x,bv0.y), bp1 = pk2(bv0.z,bv0.w);
            ull bp2 = pk2(bv1.x,bv1.y), bp3 = pk2(bv1.z,bv1.w);
            float aarr[8] = {av0.x,av0.y,av0.z,av0.w,av1.x,av1.y,av1.z,av1.w};
#pragma unroll
            for (int i=0;i<8;i++){
                ull aa = pk2(aarr[i], aarr[i]);
                fma2(acc[i][0], aa, bp0);
                fma2(acc[i][1], aa, bp1);
                fma2(acc[i][2], aa, bp2);
                fma2(acc[i][3], aa, bp3);
            }
        }
        if (more) {
            int nx = cur ^ 1;
            As[nx][0][t]=a0.x; As[nx][1][t]=a0.y; As[nx][2][t]=a0.z; As[nx][3][t]=a0.w;
            As[nx][4][t]=a1.x; As[nx][5][t]=a1.y; As[nx][6][t]=a1.z; As[nx][7][t]=a1.w;
            *(float4*)&Bs[nx][t>>3][(t&7)<<2] = b0;
            *(float4*)&Bs[nx][t>>3][((t&7)<<2)+32] = b1;
            __syncthreads();
        }
    }

    int col = (cb<<6) + (tx<<3);
    float4 bb0 = make_float4(0.f,0.f,0.f,0.f), bb1 = bb0;
    if (biasv) { bb0 = *(const float4*)(biasv + col); bb1 = *(const float4*)(biasv + col + 4); }
#pragma unroll
    for (int i=0;i<8;i++){
        int r = row0 + (ty<<3) + i;
        float2 p0=up2(acc[i][0]), p1=up2(acc[i][1]), p2=up2(acc[i][2]), p3=up2(acc[i][3]);
        float4 o0 = make_float4(p0.x+bb0.x, p0.y+bb0.y, p1.x+bb0.z, p1.y+bb0.w);
        float4 o1 = make_float4(p2.x+bb1.x, p2.y+bb1.y, p3.x+bb1.z, p3.y+bb1.w);
        *(float4*)(C + (size_t)r*Nn + col) = o0;
        *(float4*)(C + (size_t)r*Nn + col + 4) = o1;
    }
}

// ---------------- adaLN combine: an = sigmoid(tg+bg)*lna + tk ---------------
__global__ void adaln_combine_kernel(const float* __restrict__ tgk,
                                     const float* __restrict__ bgv,
                                     float* __restrict__ outp)
{
    int i = blockIdx.x*256 + threadIdx.x;
    int r = i / CD, c = i - r*CD;
    float tg = tgk[(size_t)r*1536 + c];
    float tk = tgk[(size_t)r*1536 + 768 + c];
    outp[i] = sigm(tg + bgv[c])*g_lna[i] + tk;
}

// ---------------- pair-bias precompute: wgp, packed h-pairs, c1/c2 ----------
__global__ void pair_prep_kernel(const float* __restrict__ gp,
                                 const float* __restrict__ bp,
                                 const float* __restrict__ wp)
{
    int j = threadIdx.x;  // 128
    float wg[NH];
#pragma unroll
    for (int h=0; h<NH; h++){ wg[h] = gp[j]*wp[j*NH+h]; g_wgp[j*NH+h] = wg[h]; }
#pragma unroll
    for (int m=0; m<8; m++) g_wpk[m*CPD + j] = pk2(wg[2*m], wg[2*m+1]);
    __syncthreads();
    if (j < NH) {
        float c1=0.f, c2=0.f;
        for (int jj=0; jj<CPD; jj++){ c1 += bp[jj]*wp[jj*NH+j]; c2 += g_wgp[jj*NH+j]; }
        g_cc[j]=c1; g_cc[NH+j]=c2;
    }
}

// ---------------- pair bias v3b: thread owns 4 pairs, weights broadcast -----
#define PB_SMEM (512*36*4 + 128*8*8)
__global__ void __launch_bounds__(128) pair_bias_kernel(
    const float* __restrict__ pair, const float* __restrict__ beta)
{
    extern __shared__ __align__(16) float smem[];
    float* xs = smem;                         // [512][36]
    ull* wks = (ull*)(smem + 512*36);         // [128 k][8 m]
    __shared__ float csm[2*NH];

    int t = threadIdx.x;
    int q = blockIdx.x >> 1;
    int k0 = (blockIdx.x & 1) << 9;

    for (int i = t; i < 1024; i += 128) {
        int k = i >> 3, m = i & 7;
        wks[(k<<3) + m] = g_wpk[m*CPD + k];
    }
    if (t < 2*NH) csm[t] = g_cc[t];

    ull acc[4][8];
#pragma unroll
    for (int i=0;i<4;i++)
#pragma unroll
        for (int m=0;m<8;m++) acc[i][m]=0ull;
    float sm[4] = {0.f,0.f,0.f,0.f};
    float sq[4] = {0.f,0.f,0.f,0.f};

    const float* base = pair + (((size_t)q<<10) + k0)*CPD;

    for (int c = 0; c < 4; c++) {
        __syncthreads();
#pragma unroll
        for (int it=0; it<32; it++) {
            int g = (it<<7) + t;
            int row = g >> 3, j = g & 7;
            *(float4*)(xs + row*36 + (j<<2)) =
                *(const float4*)(base + (size_t)row*CPD + (c<<5) + (j<<2));
        }
        __syncthreads();
#pragma unroll
        for (int kk=0; kk<32; kk++) {
            const ull* wr = wks + ((c<<5)+kk)*8;
            ull w0=wr[0], w1=wr[1], w2=wr[2], w3=wr[3];
            ull w4=wr[4], w5=wr[5], w6=wr[6], w7=wr[7];
#pragma unroll
            for (int i=0;i<4;i++){
                float xv = xs[(t + (i<<7))*36 + kk];
                sm[i] += xv;
                sq[i] = fmaf(xv, xv, sq[i]);
                ull xx = pk2(xv, xv);
                fma2(acc[i][0], xx, w0); fma2(acc[i][1], xx, w1);
                fma2(acc[i][2], xx, w2); fma2(acc[i][3], xx, w3);
                fma2(acc[i][4], xx, w4); fma2(acc[i][5], xx, w5);
                fma2(acc[i][6], xx, w6); fma2(acc[i][7], xx, w7);
            }
        }
    }

#pragma unroll
    for (int i=0;i<4;i++){
        int p = t + (i<<7);
        int kk = k0 + p;
        float mu = sm[i]*(1.f/128.f);
        float rs = rsqrtf(sq[i]*(1.f/128.f) - mu*mu + 1e-5f);
        float murs = mu*rs;
        float bv = beta[((size_t)q<<10) + kk];
#pragma unroll
        for (int m=0;m<8;m++){
            float2 v = up2(acc[i][m]);
            int h0 = m<<1;
            float z0 = rs*v.x - murs*csm[NH+h0]   + csm[h0]   + bv;
            float z1 = rs*v.y - murs*csm[NH+h0+1] + csm[h0+1] + bv;
            g_bias[((size_t)h0<<20)     + ((size_t)q<<10) + kk] = z0;
            g_bias[((size_t)(h0+1)<<20) + ((size_t)q<<10) + kk] = z1;
        }
    }
}

// ---------------- flash attention (f32x2) + fused output gate (R9) ----------
__global__ void __launch_bounds__(128) attn_kernel(
    const float* __restrict__ qp, const float* __restrict__ kp,
    const float* __restrict__ vp, const float* __restrict__ gatep)
{
    __shared__ __align__(16) float pool[6144];
    __shared__ float Ms[64], Ls[64];
    int t = threadIdx.x;
    int half = t>>6, ql = t&63;
    int h = blockIdx.y;
    int qr = (blockIdx.x<<6) + ql;
    const float scale = 0.14433756729740643f;
    ull q2[24];
#pragma unroll
    for (int d4=0; d4<12; d4++){
        float4 qq = *(const float4*)(qp + (size_t)qr*3072 + h*48 + (d4<<2));
        q2[d4*2]   = pk2(qq.x*scale, qq.y*scale);
        q2[d4*2+1] = pk2(qq.z*scale, qq.w*scale);
    }
    float m = -1e30f, l = 0.f;
    ull acc2[24];
#pragma unroll
    for (int i=0;i<24;i++) acc2[i]=0ull;
    int kb = half<<9;
    const float* brow = g_bias + ((size_t)h<<20) + ((size_t)qr<<10) + kb;
    for (int kt=0; kt<512; kt+=32) {
        __syncthreads();
#pragma unroll
        for (int it=0; it<6; it++) {
            int i4 = t + (it<<7);
            int d4 = i4 % 12;
            int rem = i4 / 12;
            int j = rem & 31, hh = rem >> 5;
            int krow = (hh<<9) + kt + j;
            ((float4*)pool)[i4]      = *(const float4*)(kp + (size_t)krow*3072 + h*48 + (d4<<2));
            ((float4*)pool)[768+i4]  = *(const float4*)(vp + (size_t)krow*3072 + h*48 + (d4<<2));
        }
        __syncthreads();
        float bb[32];
#pragma unroll
        for (int i=0;i<8;i++){
            float4 b4 = *(const float4*)(brow + kt + (i<<2));
            bb[i*4]=b4.x; bb[i*4+1]=b4.y; bb[i*4+2]=b4.z; bb[i*4+3]=b4.w;
        }
        const float* Kt = pool + half*1536;
        const float* Vt = pool + 3072 + half*1536;
        for (int j=0; j<32; j++) {
            const ull* kr2 = (const ull*)(Kt + j*48);
            ull d2 = 0ull;
#pragma unroll
            for (int i=0;i<24;i++) fma2(d2, q2[i], kr2[i]);
            float2 dd = up2(d2);
            float sc = dd.x + dd.y + bb[j];
            if (sc > m) {
                float corr = __expf(m - sc);
                l *= corr;
                ull cp = pk2(corr, corr);
#pragma unroll
                for (int i=0;i<24;i++) acc2[i] = mul2(acc2[i], cp);
                m = sc;
            }
            float pw = __expf(sc - m);
            l += pw;
            ull pp = pk2(pw, pw);
            const ull* vr2 = (const ull*)(Vt + j*48);
#pragma unroll
            for (int i=0;i<24;i++) fma2(acc2[i], pp, vr2[i]);
        }
    }
    __syncthreads();
    if (half == 1) {
        Ms[ql]=m; Ls[ql]=l;
#pragma unroll
        for (int i=0;i<24;i++){
            float2 v = up2(acc2[i]);
            pool[ql*48+2*i]=v.x; pool[ql*48+2*i+1]=v.y;
        }
    }
    __syncthreads();
    if (half == 0) {
        float m2=Ms[ql], l2=Ls[ql];
        float mn=fmaxf(m,m2);
        float c1=__expf(m-mn), c2=__expf(m2-mn);
        float inv=1.f/(l*c1 + l2*c2);
#pragma unroll
        for (int i=0;i<24;i++){
            float2 v = up2(acc2[i]);
            float g0 = sigm(gatep[(size_t)qr*3072 + h*48 + 2*i]);
            float g1 = sigm(gatep[(size_t)qr*3072 + h*48 + 2*i+1]);
            g_o[(size_t)qr*CD + h*48 + 2*i]   = (v.x*c1 + pool[ql*48+2*i]*c2)*inv*g0;
            g_o[(size_t)qr*CD + h*48 + 2*i+1] = (v.y*c1 + pool[ql*48+2*i+1]*c2)*inv*g1;
        }
    }
}

// ---------------- small elementwise kernels ---------------------------------
__global__ void bout_kernel(const float* __restrict__ bso) {
    int i = blockIdx.x*256 + threadIdx.x;
    int r = i / CD, c = i - r*CD;
    float att = g_attout[i] + g_attout[NT*CD + i];
    g_bout[i] = sigm(g_ts2[(size_t)r*1536 + c] + bso[c])*att;
}
__global__ void swiglu_kernel() {
    int i = blockIdx.x*256 + threadIdx.x;
    int r = i / HD, c = i - r*HD;
    float x = g_h12[(size_t)r*3072 + c];
    float y = g_h12[(size_t)r*3072 + 1536 + c];
    g_h1[i] = x*sigm(x)*y;
}
__global__ void final_kernel(const float* __restrict__ bs2, float* __restrict__ outp) {
    int i = blockIdx.x*256 + threadIdx.x;
    int r = i / CD, c = i - r*CD;
    float t3 = g_t3[i] + g_t3[NT*CD + i];
    outp[i] = g_bout[i] + sigm(g_ts2[(size_t)r*1536 + 768 + c] + bs2[c])*t3;
}

// ---------------- launch: dual-stream overlap --------------------------------
extern "C" void kernel_launch(void* const* d_in, const int* in_sizes, int n_in,
                              void* d_out, int out_size)
{
    (void)in_sizes; (void)n_in; (void)out_size;
    const float* a     = (const float*)d_in[0];
    const float* s     = (const float*)d_in[1];
    const float* pair  = (const float*)d_in[2];
    const float* beta  = (const float*)d_in[3];
    const float* sg1   = (const float*)d_in[4];
    const float* wg1   = (const float*)d_in[5];
    const float* bg1   = (const float*)d_in[6];
    const float* wsk1  = (const float*)d_in[7];
    const float* wq    = (const float*)d_in[8];
    const float* bq    = (const float*)d_in[9];
    const float* wk    = (const float*)d_in[10];
    const float* wv    = (const float*)d_in[11];
    const float* gp    = (const float*)d_in[12];
    const float* bp    = (const float*)d_in[13];
    const float* wp    = (const float*)d_in[14];
    const float* wgate = (const float*)d_in[15];
    const float* wo    = (const float*)d_in[16];
    const float* wso   = (const float*)d_in[17];
    const float* bso   = (const float*)d_in[18];
    const float* sg2   = (const float*)d_in[19];
    const float* wg2   = (const float*)d_in[20];
    const float* bg2   = (const float*)d_in[21];
    const float* wsk2  = (const float*)d_in[22];
    const float* w1    = (const float*)d_in[23];
    const float* w2    = (const float*)d_in[24];
    const float* w3    = (const float*)d_in[25];
    const float* ws2   = (const float*)d_in[26];
    const float* bs2   = (const float*)d_in[27];

    float *p_sn1,*p_sn2,*p_an,*p_an2,*p_o,*p_attout,*p_h1,*p_t3,*p_tgk,*p_tgk2,
          *p_qkvg,*p_ts2,*p_h12,*p_bqkv;
    cudaGetSymbolAddress((void**)&p_sn1,   g_sn1);
    cudaGetSymbolAddress((void**)&p_sn2,   g_sn2);
    cudaGetSymbolAddress((void**)&p_an,    g_an);
    cudaGetSymbolAddress((void**)&p_an2,   g_an2);
    cudaGetSymbolAddress((void**)&p_o,     g_o);
    cudaGetSymbolAddress((void**)&p_attout,g_attout);
    cudaGetSymbolAddress((void**)&p_h1,    g_h1);
    cudaGetSymbolAddress((void**)&p_t3,    g_t3);
    cudaGetSymbolAddress((void**)&p_tgk,   g_tgk);
    cudaGetSymbolAddress((void**)&p_tgk2,  g_tgk2);
    cudaGetSymbolAddress((void**)&p_qkvg,  g_qkvg);
    cudaGetSymbolAddress((void**)&p_ts2,   g_ts2);
    cudaGetSymbolAddress((void**)&p_h12,   g_h12);
    cudaGetSymbolAddress((void**)&p_bqkv,  g_bqkv);

    static cudaStream_t s1 = nullptr;
    static cudaEvent_t eFork, ePair, eTs2, eT3;
    if (!s1) {
        cudaFuncSetAttribute(pair_bias_kernel,
                             cudaFuncAttributeMaxDynamicSharedMemorySize, PB_SMEM);
        cudaStreamCreateWithFlags(&s1, cudaStreamNonBlocking);
        cudaEventCreateWithFlags(&eFork, cudaEventDisableTiming);
        cudaEventCreateWithFlags(&ePair, cudaEventDisableTiming);
        cudaEventCreateWithFlags(&eTs2,  cudaEventDisableTiming);
        cudaEventCreateWithFlags(&eT3,   cudaEventDisableTiming);
    }

    // ---- prep (legacy stream) ----
    ln_kernel<<<NT, 256>>>(a, s, sg1, sg2);
    pair_prep_kernel<<<1, 128>>>(gp, bp, wp);
    bfill_kernel<<<12, 256>>>(bq);

    // ---- fork: s1 carries pair_bias + ts2 + transition chain ----
    cudaEventRecord(eFork, 0);
    cudaStreamWaitEvent(s1, eFork, 0);

    pair_bias_kernel<<<2048, 128, PB_SMEM, s1>>>(pair, beta);
    cudaEventRecord(ePair, s1);
    sgemm64_kernel<<<dim3(24,16,1), 64, 0, s1>>>(s, CD, wso, ws2, wso, wso, CD,
                                                 nullptr, p_ts2, 1536, CD, 0);
    cudaEventRecord(eTs2, s1);
    sgemm64_kernel<<<dim3(24,16,1), 64, 0, s1>>>(p_sn2, CD, wg2, wsk2, wg2, wg2, CD,
                                                 nullptr, p_tgk2, 1536, CD, 0);
    adaln_combine_kernel<<<NT*CD/256, 256, 0, s1>>>(p_tgk2, bg2, p_an2);
    sgemm64_kernel<<<dim3(48,16,1), 64, 0, s1>>>(p_an2, CD, w1, w2, w1, w1, HD,
                                                 nullptr, p_h12, 3072, CD, 0);
    swiglu_kernel<<<NT*HD/256, 256, 0, s1>>>();
    sgemm64_kernel<<<dim3(12,16,2), 64, 0, s1>>>(p_h1, HD, w3, w3, w3, w3, CD,
                                                 nullptr, p_t3, CD, CD, NT*CD);
    cudaEventRecord(eT3, s1);

    // ---- legacy stream: attention chain ----
    sgemm64_kernel<<<dim3(24,16,1), 64>>>(p_sn1, CD, wg1, wsk1, wg1, wg1, CD,
                                          nullptr, p_tgk, 1536, CD, 0);
    adaln_combine_kernel<<<NT*CD/256, 256>>>(p_tgk, bg1, p_an);
    sgemm64_kernel<<<dim3(48,16,1), 64>>>(p_an, CD, wq, wk, wv, wgate, CD,
                                          p_bqkv, p_qkvg, 3072, CD, 0);
    cudaStreamWaitEvent(0, ePair, 0);
    attn_kernel<<<dim3(16, 16), 128>>>(p_qkvg, p_qkvg + 768, p_qkvg + 1536, p_qkvg + 2304);
    sgemm64_kernel<<<dim3(12,16,2), 64>>>(p_o, CD, wo, wo, wo, wo, CD,
                                          nullptr, p_attout, CD, 384, NT*CD);
    cudaStreamWaitEvent(0, eTs2, 0);
    bout_kernel<<<NT*CD/256, 256>>>(bso);
    cudaStreamWaitEvent(0, eT3, 0);       // join s1 back before final
    final_kernel<<<NT*CD/256, 256>>>(bs2, (float*)d_out);
}